// round 4
// baseline (speedup 1.0000x reference)
#include <cuda_runtime.h>
#include <cstdint>

// u: [16384, 2, 2048] float32 -> out: [16384, 2, 2048] float32
// du = 6th-order central diff along l (interior [10, 2038)), zero in ghosts.
// out[:,0,:] = -(u1*du0 + u0*du1)
// out[:,1,:] = -(2*du0 + u1*du1)

#define L 2048
#define IGST 10
#define ROW 4096            // 2 channels * L
#define ROWS_PER_BLK 8
#define S_F4 1028           // [1 f4 pad][512 ch0][2 pad][512 ch1][1 pad]
#define CH0_F4 1
#define CH1_F4 515

__device__ __forceinline__ void cp_async16(float4* smem_dst, const float4* gmem_src) {
    uint32_t s = (uint32_t)__cvta_generic_to_shared(smem_dst);
    asm volatile("cp.async.cg.shared.global [%0], [%1], 16;" :: "r"(s), "l"(gmem_src));
}
__device__ __forceinline__ void cp_commit() {
    asm volatile("cp.async.commit_group;" ::: "memory");
}
template <int N>
__device__ __forceinline__ void cp_wait() {
    asm volatile("cp.async.wait_group %0;" :: "n"(N) : "memory");
}

__global__ __launch_bounds__(256) void centdif_kernel(const float* __restrict__ u,
                                                      float* __restrict__ out) {
    __shared__ float4 s4[2][S_F4];

    const int tid = threadIdx.x;
    const long row0 = (long)blockIdx.x * ROWS_PER_BLK;

    // Prefetch a full row (1024 float4) into buffer b with channel padding offsets.
    auto prefetch = [&](int b, long r) {
        const float4* __restrict__ up = (const float4*)(u + r * ROW);
#pragma unroll
        for (int i = 0; i < 4; i++) {
            const int idx = tid + i * 256;
            const int d = idx < 512 ? (idx + CH0_F4) : (idx - 512 + CH1_F4);
            cp_async16(&s4[b][d], &up[idx]);
        }
        cp_commit();
    };

    prefetch(0, row0);

    const float c = 1.0f / (60.0f * 0.012f);

#pragma unroll 1
    for (int r = 0; r < ROWS_PER_BLK; r++) {
        if (r + 1 < ROWS_PER_BLK) {
            prefetch((r + 1) & 1, row0 + r + 1);
            cp_wait<1>();   // row r's group done (in-order groups)
        } else {
            cp_wait<0>();
        }
        __syncthreads();    // make row r visible to all warps

        const float4* sb = s4[r & 1];
        float4* __restrict__ op = (float4*)(out + (row0 + r) * ROW);

#pragma unroll
        for (int i = 0; i < 2; i++) {
            const int ck = tid + i * 256;   // chunk 0..511 -> outputs l = 4*ck .. 4*ck+3
            const int l0 = 4 * ck;

            const float4 A0 = sb[ck + CH0_F4 - 1];
            const float4 B0 = sb[ck + CH0_F4];
            const float4 C0 = sb[ck + CH0_F4 + 1];
            const float4 A1 = sb[ck + CH1_F4 - 1];
            const float4 B1 = sb[ck + CH1_F4];
            const float4 C1 = sb[ck + CH1_F4 + 1];

            const float w0[12] = {A0.x, A0.y, A0.z, A0.w, B0.x, B0.y, B0.z, B0.w, C0.x, C0.y, C0.z, C0.w};
            const float w1[12] = {A1.x, A1.y, A1.z, A1.w, B1.x, B1.y, B1.z, B1.w, C1.x, C1.y, C1.z, C1.w};

            float o0[4], o1[4];
#pragma unroll
            for (int k = 0; k < 4; k++) {
                const int p = l0 + k;
                const bool in = (p >= IGST) && (p < L - IGST);
                float du0 = (-w0[k + 1] + 9.0f * w0[k + 2] - 45.0f * w0[k + 3]
                             + 45.0f * w0[k + 5] - 9.0f * w0[k + 6] + w0[k + 7]) * c;
                float du1 = (-w1[k + 1] + 9.0f * w1[k + 2] - 45.0f * w1[k + 3]
                             + 45.0f * w1[k + 5] - 9.0f * w1[k + 6] + w1[k + 7]) * c;
                du0 = in ? du0 : 0.0f;
                du1 = in ? du1 : 0.0f;
                o0[k] = -(w0[k + 4] * 0.0f + w1[k + 4] * du0 + w0[k + 4] * du1);  // simplified below
                o0[k] = -(w1[k + 4] * du0 + w0[k + 4] * du1);
                o1[k] = -(2.0f * du0 + w1[k + 4] * du1);
            }

            op[ck]       = make_float4(o0[0], o0[1], o0[2], o0[3]);
            op[512 + ck] = make_float4(o1[0], o1[1], o1[2], o1[3]);
        }
        __syncthreads();    // all warps done reading buf before it is refilled
    }
}

extern "C" void kernel_launch(void* const* d_in, const int* in_sizes, int n_in,
                              void* d_out, int out_size) {
    const float* u = (const float*)d_in[0];
    float* out = (float*)d_out;
    const int m = in_sizes[0] / ROW;          // 16384
    centdif_kernel<<<m / ROWS_PER_BLK, 256>>>(u, out);
}

// round 5
// speedup vs baseline: 1.0827x; 1.0827x over previous
#include <cuda_runtime.h>

// u: [16384, 2, 2048] float32 -> out: [16384, 2, 2048] float32
// du = 6th-order central diff along l (interior [10, 2038)), zero in ghosts.
// out[:,0,:] = -(u1*du0 + u0*du1)
// out[:,1,:] = -(2*du0 + u1*du1)

#define L 2048
#define IGST 10
#define ROW 4096           // 2 channels * L
#define S_F4 1028          // [1 f4 pad][512 ch0][2 pad][512 ch1][1 pad]
#define CH0_F4 1
#define CH1_F4 515

__device__ __forceinline__ int smem_dest(int idx) {
    return idx < 512 ? (idx + CH0_F4) : (idx - 512 + CH1_F4);
}

__device__ __forceinline__ void compute_store(const float4* __restrict__ sb,
                                              float4* __restrict__ op, int tid) {
    const float c = 1.0f / (60.0f * 0.012f);
#pragma unroll
    for (int i = 0; i < 2; i++) {
        const int ck = tid + i * 256;   // chunk 0..511 -> outputs l = 4*ck .. 4*ck+3
        const int l0 = 4 * ck;

        const float4 A0 = sb[ck + CH0_F4 - 1];
        const float4 B0 = sb[ck + CH0_F4];
        const float4 C0 = sb[ck + CH0_F4 + 1];
        const float4 A1 = sb[ck + CH1_F4 - 1];
        const float4 B1 = sb[ck + CH1_F4];
        const float4 C1 = sb[ck + CH1_F4 + 1];

        const float w0[12] = {A0.x, A0.y, A0.z, A0.w, B0.x, B0.y, B0.z, B0.w, C0.x, C0.y, C0.z, C0.w};
        const float w1[12] = {A1.x, A1.y, A1.z, A1.w, B1.x, B1.y, B1.z, B1.w, C1.x, C1.y, C1.z, C1.w};

        float o0[4], o1[4];
#pragma unroll
        for (int k = 0; k < 4; k++) {
            const int p = l0 + k;
            const bool in = (p >= IGST) && (p < L - IGST);
            float du0 = (-w0[k + 1] + 9.0f * w0[k + 2] - 45.0f * w0[k + 3]
                         + 45.0f * w0[k + 5] - 9.0f * w0[k + 6] + w0[k + 7]) * c;
            float du1 = (-w1[k + 1] + 9.0f * w1[k + 2] - 45.0f * w1[k + 3]
                         + 45.0f * w1[k + 5] - 9.0f * w1[k + 6] + w1[k + 7]) * c;
            du0 = in ? du0 : 0.0f;
            du1 = in ? du1 : 0.0f;
            const float u0 = w0[k + 4];
            const float u1 = w1[k + 4];
            o0[k] = -(u1 * du0 + u0 * du1);
            o1[k] = -(2.0f * du0 + u1 * du1);
        }

        op[ck]       = make_float4(o0[0], o0[1], o0[2], o0[3]);
        op[512 + ck] = make_float4(o1[0], o1[1], o1[2], o1[3]);
    }
}

__global__ __launch_bounds__(256) void centdif_kernel(const float* __restrict__ u,
                                                      float* __restrict__ out) {
    __shared__ float4 s4[S_F4];

    const int tid = threadIdx.x;
    const long row0 = (long)blockIdx.x * 2;
    const float4* __restrict__ up0 = (const float4*)(u + row0 * ROW);
    const float4* __restrict__ up1 = up0 + 1024;

    // Front-batched loads for BOTH rows: 8 LDG.128 in flight per thread.
    float4 r0[4], r1[4];
#pragma unroll
    for (int i = 0; i < 4; i++) r0[i] = up0[tid + i * 256];
#pragma unroll
    for (int i = 0; i < 4; i++) r1[i] = up1[tid + i * 256];

    // Row 0: stage to smem, compute, store (row 1 loads still landing in regs).
#pragma unroll
    for (int i = 0; i < 4; i++) s4[smem_dest(tid + i * 256)] = r0[i];
    __syncthreads();
    compute_store(s4, (float4*)(out + row0 * ROW), tid);
    __syncthreads();

    // Row 1.
#pragma unroll
    for (int i = 0; i < 4; i++) s4[smem_dest(tid + i * 256)] = r1[i];
    __syncthreads();
    compute_store(s4, (float4*)(out + (row0 + 1) * ROW), tid);
}

extern "C" void kernel_launch(void* const* d_in, const int* in_sizes, int n_in,
                              void* d_out, int out_size) {
    const float* u = (const float*)d_in[0];
    float* out = (float*)d_out;
    const int m = in_sizes[0] / ROW;      // 16384
    centdif_kernel<<<m / 2, 256>>>(u, out);
}

// round 6
// speedup vs baseline: 1.0915x; 1.0082x over previous
#include <cuda_runtime.h>

// u: [16384, 2, 2048] float32 -> out: [16384, 2, 2048] float32
// du = 6th-order central diff along l (interior [10, 2038)), zero in ghosts.
// out[:,0,:] = -(u1*du0 + u0*du1)
// out[:,1,:] = -(2*du0 + u1*du1)
// R2 structure (best: 75.8us kernel, DRAM 80%) + streaming cache hints (.cs)
// on the zero-reuse global streams to cut L2 pollution.

#define L 2048
#define IGST 10
#define ROW 4096           // 2 channels * L
#define S_F4 1028          // [1 f4 pad][512 f4 ch0][2 f4 pad][512 f4 ch1][1 f4 pad]
#define CH0_F4 1
#define CH1_F4 515

__global__ __launch_bounds__(256) void centdif_kernel(const float* __restrict__ u,
                                                      float* __restrict__ out) {
    __shared__ float4 s4[S_F4];

    const int tid = threadIdx.x;
    const long base = (long)blockIdx.x * ROW;

    // Cooperative vector load of the row: 1024 float4, streaming (evict-first).
    const float4* __restrict__ up = (const float4*)(u + base);
#pragma unroll
    for (int i = 0; i < 4; i++) {
        const int idx = tid + i * 256;
        s4[idx < 512 ? (idx + CH0_F4) : (idx - 512 + CH1_F4)] = __ldcs(&up[idx]);
    }
    __syncthreads();

    const float c = 1.0f / (60.0f * 0.012f);
    float4* __restrict__ op = (float4*)(out + base);

#pragma unroll
    for (int i = 0; i < 2; i++) {
        const int ck = tid + i * 256;     // chunk 0..511 -> outputs l = 4*ck .. 4*ck+3
        const int l0 = 4 * ck;

        const float4 A0 = s4[ck + CH0_F4 - 1];
        const float4 B0 = s4[ck + CH0_F4];
        const float4 C0 = s4[ck + CH0_F4 + 1];
        const float4 A1 = s4[ck + CH1_F4 - 1];
        const float4 B1 = s4[ck + CH1_F4];
        const float4 C1 = s4[ck + CH1_F4 + 1];

        const float w0[12] = {A0.x, A0.y, A0.z, A0.w, B0.x, B0.y, B0.z, B0.w, C0.x, C0.y, C0.z, C0.w};
        const float w1[12] = {A1.x, A1.y, A1.z, A1.w, B1.x, B1.y, B1.z, B1.w, C1.x, C1.y, C1.z, C1.w};

        float o0[4], o1[4];
#pragma unroll
        for (int k = 0; k < 4; k++) {
            const int p = l0 + k;
            const bool in = (p >= IGST) && (p < L - IGST);
            float du0 = (-w0[k + 1] + 9.0f * w0[k + 2] - 45.0f * w0[k + 3]
                         + 45.0f * w0[k + 5] - 9.0f * w0[k + 6] + w0[k + 7]) * c;
            float du1 = (-w1[k + 1] + 9.0f * w1[k + 2] - 45.0f * w1[k + 3]
                         + 45.0f * w1[k + 5] - 9.0f * w1[k + 6] + w1[k + 7]) * c;
            du0 = in ? du0 : 0.0f;
            du1 = in ? du1 : 0.0f;
            const float u0 = w0[k + 4];
            const float u1 = w1[k + 4];
            o0[k] = -(u1 * du0 + u0 * du1);
            o1[k] = -(2.0f * du0 + u1 * du1);
        }

        __stcs(&op[ck],       make_float4(o0[0], o0[1], o0[2], o0[3]));
        __stcs(&op[512 + ck], make_float4(o1[0], o1[1], o1[2], o1[3]));
    }
}

extern "C" void kernel_launch(void* const* d_in, const int* in_sizes, int n_in,
                              void* d_out, int out_size) {
    const float* u = (const float*)d_in[0];
    float* out = (float*)d_out;
    const int m = in_sizes[0] / ROW;  // 16384
    centdif_kernel<<<m, 256>>>(u, out);
}